// round 1
// baseline (speedup 1.0000x reference)
#include <cuda_runtime.h>
#include <math.h>
#include <float.h>

#define B_ 2
#define T_ 2048
#define C_ 2048
#define H_ 16
#define D_ 128
#define F_ (3*C_)

// ---------------- scratch (device globals; no runtime allocation) ----------------
__device__ float g_qkv[(size_t)B_ * T_ * F_];      // [B*T, 6144]
__device__ float g_q[(size_t)B_ * H_ * T_ * D_];   // [B,H,T,D]
__device__ float g_k[(size_t)B_ * H_ * T_ * D_];
__device__ float g_v[(size_t)B_ * H_ * T_ * D_];
__device__ float g_y[(size_t)B_ * T_ * C_];        // [B*T, C]

// ---------------- GEMM: C[m][n] = sum_k A[m][k] * B[n][k] ----------------
// 128x128 tile, K-step 8, 256 threads, 8x8 micro-tile per thread.
__global__ __launch_bounds__(256) void gemm_nt(const float* __restrict__ A,
                                               const float* __restrict__ Bm,
                                               float* __restrict__ Cm,
                                               int M, int N, int K)
{
    __shared__ float As[8][128];
    __shared__ float Bs[8][128];

    const int tid = threadIdx.x;
    const int tx = tid & 15;
    const int ty = tid >> 4;
    const int m0 = blockIdx.y * 128;
    const int n0 = blockIdx.x * 128;

    const int lr = tid >> 1;          // 0..127 : tile row to load
    const int lc = (tid & 1) * 4;     // 0 or 4 : k-col group

    const float* Ab = A + (size_t)(m0 + lr) * K + lc;
    const float* Bb = Bm + (size_t)(n0 + lr) * K + lc;

    float acc[8][8];
#pragma unroll
    for (int i = 0; i < 8; i++)
#pragma unroll
        for (int j = 0; j < 8; j++) acc[i][j] = 0.f;

    for (int k0 = 0; k0 < K; k0 += 8) {
        float4 av = *(const float4*)(Ab + k0);
        float4 bv = *(const float4*)(Bb + k0);
        As[lc + 0][lr] = av.x; As[lc + 1][lr] = av.y;
        As[lc + 2][lr] = av.z; As[lc + 3][lr] = av.w;
        Bs[lc + 0][lr] = bv.x; Bs[lc + 1][lr] = bv.y;
        Bs[lc + 2][lr] = bv.z; Bs[lc + 3][lr] = bv.w;
        __syncthreads();

#pragma unroll
        for (int kk = 0; kk < 8; kk++) {
            float4 a0 = *(const float4*)&As[kk][ty * 8];
            float4 a1 = *(const float4*)&As[kk][ty * 8 + 4];
            float4 b0 = *(const float4*)&Bs[kk][tx * 8];
            float4 b1 = *(const float4*)&Bs[kk][tx * 8 + 4];
            float a[8] = {a0.x, a0.y, a0.z, a0.w, a1.x, a1.y, a1.z, a1.w};
            float b[8] = {b0.x, b0.y, b0.z, b0.w, b1.x, b1.y, b1.z, b1.w};
#pragma unroll
            for (int i = 0; i < 8; i++)
#pragma unroll
                for (int j = 0; j < 8; j++)
                    acc[i][j] = fmaf(a[i], b[j], acc[i][j]);
        }
        __syncthreads();
    }

#pragma unroll
    for (int i = 0; i < 8; i++) {
        float* cp = Cm + (size_t)(m0 + ty * 8 + i) * N + n0 + tx * 8;
        float4 c0 = {acc[i][0], acc[i][1], acc[i][2], acc[i][3]};
        float4 c1 = {acc[i][4], acc[i][5], acc[i][6], acc[i][7]};
        *(float4*)(cp) = c0;
        *(float4*)(cp + 4) = c1;
    }
}

// ---------------- RoPE + split + gain-fold ----------------
// qkv [B*T, 6144] -> g_q/g_k/g_v [B,H,T,D]; q gets gain[h] / sqrt(D) folded in.
__global__ __launch_bounds__(256) void rope_kernel(const float* __restrict__ gain,
                                                   const float* __restrict__ cosb,
                                                   const float* __restrict__ sinb)
{
    int idx = blockIdx.x * blockDim.x + threadIdx.x;  // 2^22 total
    int d = idx & 63;
    int h = (idx >> 6) & 15;
    int t = (idx >> 10) & 2047;
    int b = idx >> 21;

    size_t base = ((size_t)(b * T_ + t)) * F_ + h * D_;
    float c = cosb[t * 64 + d];
    float s = sinb[t * 64 + d];

    float q1 = g_qkv[base + d],            q2 = g_qkv[base + d + 64];
    float k1 = g_qkv[base + C_ + d],       k2 = g_qkv[base + C_ + d + 64];
    float v1 = g_qkv[base + 2 * C_ + d],   v2 = g_qkv[base + 2 * C_ + d + 64];

    float g = gain[h] * rsqrtf((float)D_);
    size_t ob = ((size_t)((b * H_ + h) * T_ + t)) * D_;

    g_q[ob + d]      = (q1 * c - q2 * s) * g;
    g_q[ob + d + 64] = (q2 * c + q1 * s) * g;
    g_k[ob + d]      = k1 * c - k2 * s;
    g_k[ob + d + 64] = k2 * c + k1 * s;
    g_v[ob + d]      = v1;
    g_v[ob + d + 64] = v2;
}

// ---------------- causal flash attention (fp32) ----------------
// Q tile 128, K tile 128, D=128. 256 threads, 8x8 micro-tiles.
// sQ, sK stored transposed [d][idx]; sV natural [k][d]; sP [k][q] stride 129.
#define PSTRIDE 129
__global__ __launch_bounds__(256, 1) void attn_kernel(float* __restrict__ Y)
{
    extern __shared__ float sm[];
    float* sQ  = sm;              // 128*128
    float* sKV = sm + 16384;      // 128*128 (K transposed, then V natural)
    float* sP  = sm + 32768;      // 128*PSTRIDE

    const int tid = threadIdx.x;
    const int tx = tid & 15;
    const int ty = tid >> 4;
    const int qb = blockIdx.x;
    const int h  = blockIdx.y;
    const int b  = blockIdx.z;
    const int q0 = qb * 128;
    const size_t bh = ((size_t)(b * H_ + h)) * T_ * D_;

    // load Q tile transposed: sQ[d][q]
    for (int i = 0; i < 16; i++) {
        int e = tid + i * 256;
        int row = e >> 5;
        int col = (e & 31) * 4;
        float4 v = *(const float4*)(g_q + bh + (size_t)(q0 + row) * D_ + col);
        sQ[(col + 0) * 128 + row] = v.x;
        sQ[(col + 1) * 128 + row] = v.y;
        sQ[(col + 2) * 128 + row] = v.z;
        sQ[(col + 3) * 128 + row] = v.w;
    }

    float acc[8][8];
    float m[8], l[8];
#pragma unroll
    for (int i = 0; i < 8; i++) {
        m[i] = -FLT_MAX;
        l[i] = 0.f;
#pragma unroll
        for (int j = 0; j < 8; j++) acc[i][j] = 0.f;
    }

    const int ntiles = qb + 1;
    for (int kt = 0; kt < ntiles; kt++) {
        const int k0 = kt * 128;

        // load K tile transposed: sKV[d][k]
        for (int i = 0; i < 16; i++) {
            int e = tid + i * 256;
            int row = e >> 5;
            int col = (e & 31) * 4;
            float4 v = *(const float4*)(g_k + bh + (size_t)(k0 + row) * D_ + col);
            sKV[(col + 0) * 128 + row] = v.x;
            sKV[(col + 1) * 128 + row] = v.y;
            sKV[(col + 2) * 128 + row] = v.z;
            sKV[(col + 3) * 128 + row] = v.w;
        }
        __syncthreads();

        // scores S = Q K^T  (8x8 per thread)
        float s[8][8];
#pragma unroll
        for (int i = 0; i < 8; i++)
#pragma unroll
            for (int j = 0; j < 8; j++) s[i][j] = 0.f;

#pragma unroll 4
        for (int kk = 0; kk < 128; kk++) {
            float4 a0 = *(const float4*)&sQ[kk * 128 + ty * 8];
            float4 a1 = *(const float4*)&sQ[kk * 128 + ty * 8 + 4];
            float4 b0 = *(const float4*)&sKV[kk * 128 + tx * 8];
            float4 b1 = *(const float4*)&sKV[kk * 128 + tx * 8 + 4];
            float a[8] = {a0.x, a0.y, a0.z, a0.w, a1.x, a1.y, a1.z, a1.w};
            float bb[8] = {b0.x, b0.y, b0.z, b0.w, b1.x, b1.y, b1.z, b1.w};
#pragma unroll
            for (int i = 0; i < 8; i++)
#pragma unroll
                for (int j = 0; j < 8; j++)
                    s[i][j] = fmaf(a[i], bb[j], s[i][j]);
        }

        // causal mask (only diagonal tile needs it)
        if (kt == qb) {
#pragma unroll
            for (int i = 0; i < 8; i++) {
                int qg = q0 + ty * 8 + i;
#pragma unroll
                for (int j = 0; j < 8; j++) {
                    int kg = k0 + tx * 8 + j;
                    if (kg > qg) s[i][j] = -FLT_MAX;
                }
            }
        }

        // online softmax update
#pragma unroll
        for (int i = 0; i < 8; i++) {
            float mx = s[i][0];
#pragma unroll
            for (int j = 1; j < 8; j++) mx = fmaxf(mx, s[i][j]);
#pragma unroll
            for (int o = 1; o < 16; o <<= 1)
                mx = fmaxf(mx, __shfl_xor_sync(0xffffffffu, mx, o));

            float mn = fmaxf(m[i], mx);
            float cf = __expf(m[i] - mn);
            m[i] = mn;

            float rs = 0.f;
#pragma unroll
            for (int j = 0; j < 8; j++) {
                float p = __expf(s[i][j] - mn);
                s[i][j] = p;
                rs += p;
            }
#pragma unroll
            for (int o = 1; o < 16; o <<= 1)
                rs += __shfl_xor_sync(0xffffffffu, rs, o);

            l[i] = l[i] * cf + rs;
#pragma unroll
            for (int j = 0; j < 8; j++) acc[i][j] *= cf;
        }

        // stage P transposed: sP[k][q]
#pragma unroll
        for (int j = 0; j < 8; j++) {
            float* pp = &sP[(size_t)(tx * 8 + j) * PSTRIDE + ty * 8];
#pragma unroll
            for (int i = 0; i < 8; i++) pp[i] = s[i][j];
        }
        __syncthreads();

        // load V tile natural: sKV[k][d]
        for (int i = 0; i < 16; i++) {
            int e = tid + i * 256;
            int row = e >> 5;
            int col = (e & 31) * 4;
            float4 v = *(const float4*)(g_v + bh + (size_t)(k0 + row) * D_ + col);
            *(float4*)&sKV[row * 128 + col] = v;
        }
        __syncthreads();

        // acc += P @ V
#pragma unroll 4
        for (int kk = 0; kk < 128; kk++) {
            const float* pr = &sP[(size_t)kk * PSTRIDE + ty * 8];
            float4 b0 = *(const float4*)&sKV[kk * 128 + tx * 8];
            float4 b1 = *(const float4*)&sKV[kk * 128 + tx * 8 + 4];
            float bb[8] = {b0.x, b0.y, b0.z, b0.w, b1.x, b1.y, b1.z, b1.w};
#pragma unroll
            for (int i = 0; i < 8; i++) {
                float p = pr[i];
#pragma unroll
                for (int j = 0; j < 8; j++)
                    acc[i][j] = fmaf(p, bb[j], acc[i][j]);
            }
        }
        __syncthreads();
    }

    // write y [B,T,C] = [B,T,H*D]
#pragma unroll
    for (int i = 0; i < 8; i++) {
        float inv = 1.f / l[i];
        float* yp = Y + ((size_t)(b * T_ + q0 + ty * 8 + i)) * C_ + h * D_ + tx * 8;
        float4 c0 = {acc[i][0] * inv, acc[i][1] * inv, acc[i][2] * inv, acc[i][3] * inv};
        float4 c1 = {acc[i][4] * inv, acc[i][5] * inv, acc[i][6] * inv, acc[i][7] * inv};
        *(float4*)(yp) = c0;
        *(float4*)(yp + 4) = c1;
    }
}

// ---------------- launch ----------------
extern "C" void kernel_launch(void* const* d_in, const int* in_sizes, int n_in,
                              void* d_out, int out_size)
{
    const float* x     = (const float*)d_in[0];
    const float* Wqkv  = (const float*)d_in[1];
    const float* Wproj = (const float*)d_in[2];
    const float* gain  = (const float*)d_in[3];
    const float* cosb  = (const float*)d_in[4];
    const float* sinb  = (const float*)d_in[5];
    float* out = (float*)d_out;

    float *qkv, *y;
    cudaGetSymbolAddress((void**)&qkv, g_qkv);
    cudaGetSymbolAddress((void**)&y, g_y);

    // 1) QKV GEMM: [4096,2048] x [6144,2048]^T -> [4096,6144]
    {
        dim3 grid(F_ / 128, (B_ * T_) / 128);
        gemm_nt<<<grid, 256>>>(x, Wqkv, qkv, B_ * T_, F_, C_);
    }

    // 2) RoPE + split + gain
    {
        int total = B_ * T_ * H_ * 64;
        rope_kernel<<<total / 256, 256>>>(gain, cosb, sinb);
    }

    // 3) attention
    {
        size_t smem = (size_t)(16384 + 16384 + 128 * PSTRIDE) * sizeof(float);
        cudaFuncSetAttribute(attn_kernel, cudaFuncAttributeMaxDynamicSharedMemorySize, (int)smem);
        dim3 grid(T_ / 128, H_, B_);
        attn_kernel<<<grid, 256, smem>>>(y);
    }

    // 4) output projection: [4096,2048] x [2048,2048]^T -> out
    {
        dim3 grid(C_ / 128, (B_ * T_) / 128);
        gemm_nt<<<grid, 256>>>(y, Wproj, out, B_ * T_, C_, C_);
    }
}

// round 2
// speedup vs baseline: 1.5129x; 1.5129x over previous
#include <cuda_runtime.h>
#include <math.h>
#include <float.h>
#include <stdint.h>

#define B_ 2
#define T_ 2048
#define C_ 2048
#define H_ 16
#define D_ 128
#define F_ (3*C_)

// ---------------- scratch (device globals; no runtime allocation) ----------------
__device__ float g_qkv[(size_t)B_ * T_ * F_];      // [B*T, 6144]
__device__ float g_q[(size_t)B_ * H_ * T_ * D_];   // [B,H,T,D]
__device__ float g_k[(size_t)B_ * H_ * T_ * D_];
__device__ float g_v[(size_t)B_ * H_ * T_ * D_];
__device__ float g_y[(size_t)B_ * T_ * C_];        // [B*T, C]

// ---------------- tf32 tensor-core GEMM: C[m][n] = sum_k A[m][k]*B[n][k] ----------
// 128x128 block tile, 8 warps (2m x 4n), warp tile 64x32, KS=16 double-buffered.
#define CVT_TF32(d, s) asm("cvt.rna.tf32.f32 %0, %1;" : "=r"(d) : "f"(s))

#define MMA_TF32(c, a, b)                                                     \
  asm volatile(                                                               \
      "mma.sync.aligned.m16n8k8.row.col.f32.tf32.tf32.f32 "                   \
      "{%0,%1,%2,%3}, {%4,%5,%6,%7}, {%8,%9}, {%0,%1,%2,%3};"                 \
      : "+f"((c)[0]), "+f"((c)[1]), "+f"((c)[2]), "+f"((c)[3])                \
      : "r"((a)[0]), "r"((a)[1]), "r"((a)[2]), "r"((a)[3]),                   \
        "r"((b)[0]), "r"((b)[1]))

#define SSTR 20  // smem row stride (floats): conflict-free for fragment LDS

__global__ __launch_bounds__(256, 1) void gemm_tf32(const float* __restrict__ A,
                                                    const float* __restrict__ Bm,
                                                    float* __restrict__ Cm,
                                                    int M, int N, int K)
{
    __shared__ __align__(16) uint32_t As[2][128][SSTR];
    __shared__ __align__(16) uint32_t Bs[2][128][SSTR];

    const int tid  = threadIdx.x;
    const int warp = tid >> 5;
    const int lane = tid & 31;
    const int g    = lane >> 2;
    const int tg   = lane & 3;
    const int wm   = (warp & 1) * 64;
    const int wn   = (warp >> 1) * 32;
    const int m0   = blockIdx.y * 128;
    const int n0   = blockIdx.x * 128;

    const int lrow = tid >> 1;          // 0..127
    const int lkg  = (tid & 1) * 8;     // 0 or 8

    const float* Ap = A + (size_t)(m0 + lrow) * K + lkg;
    const float* Bp = Bm + (size_t)(n0 + lrow) * K + lkg;

    float acc[4][4][4];
#pragma unroll
    for (int mi = 0; mi < 4; mi++)
#pragma unroll
        for (int ni = 0; ni < 4; ni++)
#pragma unroll
            for (int c = 0; c < 4; c++) acc[mi][ni][c] = 0.f;

    // preload stage 0
    {
        float4 a0 = *(const float4*)(Ap);
        float4 a1 = *(const float4*)(Ap + 4);
        float4 b0 = *(const float4*)(Bp);
        float4 b1 = *(const float4*)(Bp + 4);
        uint32_t r[8], s[8];
        CVT_TF32(r[0], a0.x); CVT_TF32(r[1], a0.y); CVT_TF32(r[2], a0.z); CVT_TF32(r[3], a0.w);
        CVT_TF32(r[4], a1.x); CVT_TF32(r[5], a1.y); CVT_TF32(r[6], a1.z); CVT_TF32(r[7], a1.w);
        CVT_TF32(s[0], b0.x); CVT_TF32(s[1], b0.y); CVT_TF32(s[2], b0.z); CVT_TF32(s[3], b0.w);
        CVT_TF32(s[4], b1.x); CVT_TF32(s[5], b1.y); CVT_TF32(s[6], b1.z); CVT_TF32(s[7], b1.w);
        *(uint4*)&As[0][lrow][lkg]     = make_uint4(r[0], r[1], r[2], r[3]);
        *(uint4*)&As[0][lrow][lkg + 4] = make_uint4(r[4], r[5], r[6], r[7]);
        *(uint4*)&Bs[0][lrow][lkg]     = make_uint4(s[0], s[1], s[2], s[3]);
        *(uint4*)&Bs[0][lrow][lkg + 4] = make_uint4(s[4], s[5], s[6], s[7]);
    }
    __syncthreads();

    int cur = 0;
    for (int k0 = 0; k0 < K; k0 += 16) {
        const bool has_next = (k0 + 16 < K);
        uint32_t na[8], nb[8];
        if (has_next) {
            const float* ap = Ap + k0 + 16;
            const float* bp = Bp + k0 + 16;
            float4 a0 = *(const float4*)(ap);
            float4 a1 = *(const float4*)(ap + 4);
            float4 b0 = *(const float4*)(bp);
            float4 b1 = *(const float4*)(bp + 4);
            CVT_TF32(na[0], a0.x); CVT_TF32(na[1], a0.y); CVT_TF32(na[2], a0.z); CVT_TF32(na[3], a0.w);
            CVT_TF32(na[4], a1.x); CVT_TF32(na[5], a1.y); CVT_TF32(na[6], a1.z); CVT_TF32(na[7], a1.w);
            CVT_TF32(nb[0], b0.x); CVT_TF32(nb[1], b0.y); CVT_TF32(nb[2], b0.z); CVT_TF32(nb[3], b0.w);
            CVT_TF32(nb[4], b1.x); CVT_TF32(nb[5], b1.y); CVT_TF32(nb[6], b1.z); CVT_TF32(nb[7], b1.w);
        }

#pragma unroll
        for (int ks = 0; ks < 2; ks++) {
            const int kk = ks * 8;
            uint32_t af[4][4], bf[4][2];
#pragma unroll
            for (int mi = 0; mi < 4; mi++) {
                const int mr = wm + mi * 16 + g;
                af[mi][0] = As[cur][mr][kk + tg];
                af[mi][1] = As[cur][mr + 8][kk + tg];
                af[mi][2] = As[cur][mr][kk + tg + 4];
                af[mi][3] = As[cur][mr + 8][kk + tg + 4];
            }
#pragma unroll
            for (int ni = 0; ni < 4; ni++) {
                const int nr = wn + ni * 8 + g;
                bf[ni][0] = Bs[cur][nr][kk + tg];
                bf[ni][1] = Bs[cur][nr][kk + tg + 4];
            }
#pragma unroll
            for (int mi = 0; mi < 4; mi++)
#pragma unroll
                for (int ni = 0; ni < 4; ni++)
                    MMA_TF32(acc[mi][ni], af[mi], bf[ni]);
        }

        if (has_next) {
            *(uint4*)&As[cur ^ 1][lrow][lkg]     = make_uint4(na[0], na[1], na[2], na[3]);
            *(uint4*)&As[cur ^ 1][lrow][lkg + 4] = make_uint4(na[4], na[5], na[6], na[7]);
            *(uint4*)&Bs[cur ^ 1][lrow][lkg]     = make_uint4(nb[0], nb[1], nb[2], nb[3]);
            *(uint4*)&Bs[cur ^ 1][lrow][lkg + 4] = make_uint4(nb[4], nb[5], nb[6], nb[7]);
        }
        __syncthreads();
        cur ^= 1;
    }

    // epilogue
#pragma unroll
    for (int mi = 0; mi < 4; mi++) {
#pragma unroll
        for (int ni = 0; ni < 4; ni++) {
            const int r = m0 + wm + mi * 16 + g;
            const int c = n0 + wn + ni * 8 + 2 * tg;
            float2 v0 = {acc[mi][ni][0], acc[mi][ni][1]};
            float2 v1 = {acc[mi][ni][2], acc[mi][ni][3]};
            *(float2*)&Cm[(size_t)r * N + c]       = v0;
            *(float2*)&Cm[(size_t)(r + 8) * N + c] = v1;
        }
    }
}

// ---------------- RoPE + split + gain-fold ----------------
__global__ __launch_bounds__(256) void rope_kernel(const float* __restrict__ gain,
                                                   const float* __restrict__ cosb,
                                                   const float* __restrict__ sinb)
{
    int idx = blockIdx.x * blockDim.x + threadIdx.x;  // 2^22 total
    int d = idx & 63;
    int h = (idx >> 6) & 15;
    int t = (idx >> 10) & 2047;
    int b = idx >> 21;

    size_t base = ((size_t)(b * T_ + t)) * F_ + h * D_;
    float c = cosb[t * 64 + d];
    float s = sinb[t * 64 + d];

    float q1 = g_qkv[base + d],            q2 = g_qkv[base + d + 64];
    float k1 = g_qkv[base + C_ + d],       k2 = g_qkv[base + C_ + d + 64];
    float v1 = g_qkv[base + 2 * C_ + d],   v2 = g_qkv[base + 2 * C_ + d + 64];

    float g = gain[h] * rsqrtf((float)D_);
    size_t ob = ((size_t)((b * H_ + h) * T_ + t)) * D_;

    g_q[ob + d]      = (q1 * c - q2 * s) * g;
    g_q[ob + d + 64] = (q2 * c + q1 * s) * g;
    g_k[ob + d]      = k1 * c - k2 * s;
    g_k[ob + d + 64] = k2 * c + k1 * s;
    g_v[ob + d]      = v1;
    g_v[ob + d + 64] = v2;
}

// ---------------- causal flash attention (fp32) ----------------
#define PSTRIDE 129
__global__ __launch_bounds__(256, 1) void attn_kernel(float* __restrict__ Y)
{
    extern __shared__ float sm[];
    float* sQ  = sm;              // 128*128
    float* sKV = sm + 16384;      // 128*128 (K transposed, then V natural)
    float* sP  = sm + 32768;      // 128*PSTRIDE

    const int tid = threadIdx.x;
    const int tx = tid & 15;
    const int ty = tid >> 4;
    const int qb = blockIdx.x;
    const int h  = blockIdx.y;
    const int b  = blockIdx.z;
    const int q0 = qb * 128;
    const size_t bh = ((size_t)(b * H_ + h)) * T_ * D_;

    for (int i = 0; i < 16; i++) {
        int e = tid + i * 256;
        int row = e >> 5;
        int col = (e & 31) * 4;
        float4 v = *(const float4*)(g_q + bh + (size_t)(q0 + row) * D_ + col);
        sQ[(col + 0) * 128 + row] = v.x;
        sQ[(col + 1) * 128 + row] = v.y;
        sQ[(col + 2) * 128 + row] = v.z;
        sQ[(col + 3) * 128 + row] = v.w;
    }

    float acc[8][8];
    float m[8], l[8];
#pragma unroll
    for (int i = 0; i < 8; i++) {
        m[i] = -FLT_MAX;
        l[i] = 0.f;
#pragma unroll
        for (int j = 0; j < 8; j++) acc[i][j] = 0.f;
    }

    const int ntiles = qb + 1;
    for (int kt = 0; kt < ntiles; kt++) {
        const int k0 = kt * 128;

        for (int i = 0; i < 16; i++) {
            int e = tid + i * 256;
            int row = e >> 5;
            int col = (e & 31) * 4;
            float4 v = *(const float4*)(g_k + bh + (size_t)(k0 + row) * D_ + col);
            sKV[(col + 0) * 128 + row] = v.x;
            sKV[(col + 1) * 128 + row] = v.y;
            sKV[(col + 2) * 128 + row] = v.z;
            sKV[(col + 3) * 128 + row] = v.w;
        }
        __syncthreads();

        float s[8][8];
#pragma unroll
        for (int i = 0; i < 8; i++)
#pragma unroll
            for (int j = 0; j < 8; j++) s[i][j] = 0.f;

#pragma unroll 4
        for (int kk = 0; kk < 128; kk++) {
            float4 a0 = *(const float4*)&sQ[kk * 128 + ty * 8];
            float4 a1 = *(const float4*)&sQ[kk * 128 + ty * 8 + 4];
            float4 b0 = *(const float4*)&sKV[kk * 128 + tx * 8];
            float4 b1 = *(const float4*)&sKV[kk * 128 + tx * 8 + 4];
            float a[8] = {a0.x, a0.y, a0.z, a0.w, a1.x, a1.y, a1.z, a1.w};
            float bb[8] = {b0.x, b0.y, b0.z, b0.w, b1.x, b1.y, b1.z, b1.w};
#pragma unroll
            for (int i = 0; i < 8; i++)
#pragma unroll
                for (int j = 0; j < 8; j++)
                    s[i][j] = fmaf(a[i], bb[j], s[i][j]);
        }

        if (kt == qb) {
#pragma unroll
            for (int i = 0; i < 8; i++) {
                int qg = q0 + ty * 8 + i;
#pragma unroll
                for (int j = 0; j < 8; j++) {
                    int kg = k0 + tx * 8 + j;
                    if (kg > qg) s[i][j] = -FLT_MAX;
                }
            }
        }

#pragma unroll
        for (int i = 0; i < 8; i++) {
            float mx = s[i][0];
#pragma unroll
            for (int j = 1; j < 8; j++) mx = fmaxf(mx, s[i][j]);
#pragma unroll
            for (int o = 1; o < 16; o <<= 1)
                mx = fmaxf(mx, __shfl_xor_sync(0xffffffffu, mx, o));

            float mn = fmaxf(m[i], mx);
            float cf = __expf(m[i] - mn);
            m[i] = mn;

            float rs = 0.f;
#pragma unroll
            for (int j = 0; j < 8; j++) {
                float p = __expf(s[i][j] - mn);
                s[i][j] = p;
                rs += p;
            }
#pragma unroll
            for (int o = 1; o < 16; o <<= 1)
                rs += __shfl_xor_sync(0xffffffffu, rs, o);

            l[i] = l[i] * cf + rs;
#pragma unroll
            for (int j = 0; j < 8; j++) acc[i][j] *= cf;
        }

#pragma unroll
        for (int j = 0; j < 8; j++) {
            float* pp = &sP[(size_t)(tx * 8 + j) * PSTRIDE + ty * 8];
#pragma unroll
            for (int i = 0; i < 8; i++) pp[i] = s[i][j];
        }
        __syncthreads();

        for (int i = 0; i < 16; i++) {
            int e = tid + i * 256;
            int row = e >> 5;
            int col = (e & 31) * 4;
            float4 v = *(const float4*)(g_v + bh + (size_t)(k0 + row) * D_ + col);
            *(float4*)&sKV[row * 128 + col] = v;
        }
        __syncthreads();

#pragma unroll 4
        for (int kk = 0; kk < 128; kk++) {
            const float* pr = &sP[(size_t)kk * PSTRIDE + ty * 8];
            float4 b0 = *(const float4*)&sKV[kk * 128 + tx * 8];
            float4 b1 = *(const float4*)&sKV[kk * 128 + tx * 8 + 4];
            float bb[8] = {b0.x, b0.y, b0.z, b0.w, b1.x, b1.y, b1.z, b1.w};
#pragma unroll
            for (int i = 0; i < 8; i++) {
                float p = pr[i];
#pragma unroll
                for (int j = 0; j < 8; j++)
                    acc[i][j] = fmaf(p, bb[j], acc[i][j]);
            }
        }
        __syncthreads();
    }

#pragma unroll
    for (int i = 0; i < 8; i++) {
        float inv = 1.f / l[i];
        float* yp = Y + ((size_t)(b * T_ + q0 + ty * 8 + i)) * C_ + h * D_ + tx * 8;
        float4 c0 = {acc[i][0] * inv, acc[i][1] * inv, acc[i][2] * inv, acc[i][3] * inv};
        float4 c1 = {acc[i][4] * inv, acc[i][5] * inv, acc[i][6] * inv, acc[i][7] * inv};
        *(float4*)(yp) = c0;
        *(float4*)(yp + 4) = c1;
    }
}

// ---------------- launch ----------------
extern "C" void kernel_launch(void* const* d_in, const int* in_sizes, int n_in,
                              void* d_out, int out_size)
{
    const float* x     = (const float*)d_in[0];
    const float* Wqkv  = (const float*)d_in[1];
    const float* Wproj = (const float*)d_in[2];
    const float* gain  = (const float*)d_in[3];
    const float* cosb  = (const float*)d_in[4];
    const float* sinb  = (const float*)d_in[5];
    float* out = (float*)d_out;

    float *qkv, *y;
    cudaGetSymbolAddress((void**)&qkv, g_qkv);
    cudaGetSymbolAddress((void**)&y, g_y);

    // 1) QKV GEMM: [4096,2048] x [6144,2048]^T -> [4096,6144]
    {
        dim3 grid(F_ / 128, (B_ * T_) / 128);
        gemm_tf32<<<grid, 256>>>(x, Wqkv, qkv, B_ * T_, F_, C_);
    }

    // 2) RoPE + split + gain
    {
        int total = B_ * T_ * H_ * 64;
        rope_kernel<<<total / 256, 256>>>(gain, cosb, sinb);
    }

    // 3) attention
    {
        size_t smem = (size_t)(16384 + 16384 + 128 * PSTRIDE) * sizeof(float);
        cudaFuncSetAttribute(attn_kernel, cudaFuncAttributeMaxDynamicSharedMemorySize, (int)smem);
        dim3 grid(T_ / 128, H_, B_);
        attn_kernel<<<grid, 256, smem>>>(y);
    }

    // 4) output projection: [4096,2048] x [2048,2048]^T -> out
    {
        dim3 grid(C_ / 128, (B_ * T_) / 128);
        gemm_tf32<<<grid, 256>>>(y, Wproj, out, B_ * T_, C_, C_);
    }
}

// round 4
// speedup vs baseline: 3.4700x; 2.2937x over previous
#include <cuda_runtime.h>
#include <math.h>
#include <float.h>
#include <stdint.h>

#define B_ 2
#define T_ 2048
#define C_ 2048
#define H_ 16
#define D_ 128
#define F_ (3*C_)

// ---------------- scratch ----------------
__device__ float g_qkv[(size_t)B_ * T_ * F_];
__device__ float g_q[(size_t)B_ * H_ * T_ * D_];
__device__ float g_k[(size_t)B_ * H_ * T_ * D_];
__device__ float g_v[(size_t)B_ * H_ * T_ * D_];
__device__ float g_y[(size_t)B_ * T_ * C_];

// ---------------- helpers ----------------
#define CVT_TF32(d, s) asm("cvt.rna.tf32.f32 %0, %1;" : "=r"(d) : "f"(s))

__device__ __forceinline__ uint32_t tf32_rn(float x) {
    uint32_t r; CVT_TF32(r, x); return r;
}

#define MMA_TF32(c, a, b)                                                     \
  asm volatile(                                                               \
      "mma.sync.aligned.m16n8k8.row.col.f32.tf32.tf32.f32 "                   \
      "{%0,%1,%2,%3}, {%4,%5,%6,%7}, {%8,%9}, {%0,%1,%2,%3};"                 \
      : "+f"((c)[0]), "+f"((c)[1]), "+f"((c)[2]), "+f"((c)[3])                \
      : "r"((a)[0]), "r"((a)[1]), "r"((a)[2]), "r"((a)[3]),                   \
        "r"((b)[0]), "r"((b)[1]))

__device__ __forceinline__ void cp16(float* sdst, const float* gsrc) {
    uint32_t s = (uint32_t)__cvta_generic_to_shared(sdst);
    asm volatile("cp.async.cg.shared.global [%0], [%1], 16;" :: "r"(s), "l"(gsrc));
}
#define CP_COMMIT() asm volatile("cp.async.commit_group;" ::)
#define CP_WAIT1()  asm volatile("cp.async.wait_group 1;" ::)

// ---------------- tf32 GEMM: C[m][n] = sum_k A[m][k]*B[n][k] -----------------
// 128x128 tile, 8 warps (2m x 4n), KS=32, cp.async 2-stage, 2 CTAs/SM.
// Raw fp32 in smem; cvt.rna.tf32 at fragment-load time (RN rounding — critical).
#define GSTR 36

__global__ __launch_bounds__(256, 2) void gemm_tf32(const float* __restrict__ A,
                                                    const float* __restrict__ Bm,
                                                    float* __restrict__ Cm,
                                                    int M, int N, int K)
{
    extern __shared__ float gsm[];
    float* As = gsm;                     // [2][128][GSTR]
    float* Bs = gsm + 2 * 128 * GSTR;    // [2][128][GSTR]

    const int tid  = threadIdx.x;
    const int warp = tid >> 5;
    const int lane = tid & 31;
    const int g    = lane >> 2;
    const int tg   = lane & 3;
    const int wm   = (warp & 1) * 64;
    const int wn   = (warp >> 1) * 32;
    const int m0   = blockIdx.y * 128;
    const int n0   = blockIdx.x * 128;

    const int lrow = tid >> 3;           // 0..31
    const int lc4  = (tid & 7) << 2;     // 0,4,..28

    float acc[4][4][4];
#pragma unroll
    for (int mi = 0; mi < 4; mi++)
#pragma unroll
        for (int ni = 0; ni < 4; ni++)
#pragma unroll
            for (int c = 0; c < 4; c++) acc[mi][ni][c] = 0.f;

    auto load_stage = [&](int s, int k0) {
#pragma unroll
        for (int i = 0; i < 4; i++) {
            int row = lrow + i * 32;
            cp16(&As[(size_t)s * 128 * GSTR + row * GSTR + lc4],
                 A + (size_t)(m0 + row) * K + k0 + lc4);
            cp16(&Bs[(size_t)s * 128 * GSTR + row * GSTR + lc4],
                 Bm + (size_t)(n0 + row) * K + k0 + lc4);
        }
    };

    load_stage(0, 0);  CP_COMMIT();
    load_stage(1, 32); CP_COMMIT();
    CP_WAIT1();
    __syncthreads();

    const int nK = K / 32;
    int cur = 0;
    for (int kt = 0; kt < nK; kt++) {
        const float* Ac = As + (size_t)cur * 128 * GSTR;
        const float* Bc = Bs + (size_t)cur * 128 * GSTR;
#pragma unroll
        for (int ks = 0; ks < 4; ks++) {
            const int kk = ks * 8;
            uint32_t af[4][4], bf[4][2];
#pragma unroll
            for (int mi = 0; mi < 4; mi++) {
                const int mr = wm + mi * 16 + g;
                af[mi][0] = tf32_rn(Ac[mr * GSTR + kk + tg]);
                af[mi][1] = tf32_rn(Ac[(mr + 8) * GSTR + kk + tg]);
                af[mi][2] = tf32_rn(Ac[mr * GSTR + kk + tg + 4]);
                af[mi][3] = tf32_rn(Ac[(mr + 8) * GSTR + kk + tg + 4]);
            }
#pragma unroll
            for (int ni = 0; ni < 4; ni++) {
                const int nr = wn + ni * 8 + g;
                bf[ni][0] = tf32_rn(Bc[nr * GSTR + kk + tg]);
                bf[ni][1] = tf32_rn(Bc[nr * GSTR + kk + tg + 4]);
            }
#pragma unroll
            for (int mi = 0; mi < 4; mi++)
#pragma unroll
                for (int ni = 0; ni < 4; ni++)
                    MMA_TF32(acc[mi][ni], af[mi], bf[ni]);
        }
        __syncthreads();
        if (kt + 2 < nK) load_stage(cur, (kt + 2) * 32);
        CP_COMMIT();
        CP_WAIT1();
        __syncthreads();
        cur ^= 1;
    }

#pragma unroll
    for (int mi = 0; mi < 4; mi++) {
#pragma unroll
        for (int ni = 0; ni < 4; ni++) {
            const int r = m0 + wm + mi * 16 + g;
            const int c = n0 + wn + ni * 8 + 2 * tg;
            float2 v0 = {acc[mi][ni][0], acc[mi][ni][1]};
            float2 v1 = {acc[mi][ni][2], acc[mi][ni][3]};
            *(float2*)&Cm[(size_t)r * N + c]       = v0;
            *(float2*)&Cm[(size_t)(r + 8) * N + c] = v1;
        }
    }
}

// ---------------- RoPE + split + gain-fold ----------------
__global__ __launch_bounds__(256) void rope_kernel(const float* __restrict__ gain,
                                                   const float* __restrict__ cosb,
                                                   const float* __restrict__ sinb)
{
    int idx = blockIdx.x * blockDim.x + threadIdx.x;
    int d = idx & 63;
    int h = (idx >> 6) & 15;
    int t = (idx >> 10) & 2047;
    int b = idx >> 21;

    size_t base = ((size_t)(b * T_ + t)) * F_ + h * D_;
    float c = cosb[t * 64 + d];
    float s = sinb[t * 64 + d];

    float q1 = g_qkv[base + d],            q2 = g_qkv[base + d + 64];
    float k1 = g_qkv[base + C_ + d],       k2 = g_qkv[base + C_ + d + 64];
    float v1 = g_qkv[base + 2 * C_ + d],   v2 = g_qkv[base + 2 * C_ + d + 64];

    float g = gain[h] * rsqrtf((float)D_);
    size_t ob = ((size_t)((b * H_ + h) * T_ + t)) * D_;

    g_q[ob + d]      = (q1 * c - q2 * s) * g;
    g_q[ob + d + 64] = (q2 * c + q1 * s) * g;
    g_k[ob + d]      = k1 * c - k2 * s;
    g_k[ob + d + 64] = k2 * c + k1 * s;
    g_v[ob + d]      = v1;
    g_v[ob + d + 64] = v2;
}

// ---------------- tensor-core causal flash attention (tf32, RN everywhere) ----
#define QSTR 132
#define KSTR 132
#define VSTR 136
#define PSTR 132

__global__ __launch_bounds__(256, 1) void attn_tc(float* __restrict__ Y)
{
    extern __shared__ float sm[];
    float* sQ  = sm;                         // [128][QSTR] tf32 bits
    float* sKV = sm + 128 * QSTR;            // [128][VSTR/KSTR] raw fp32
    float* sP  = sKV + 128 * VSTR;           // [128][PSTR] tf32 bits

    const int tid  = threadIdx.x;
    const int warp = tid >> 5;
    const int lane = tid & 31;
    const int g    = lane >> 2;
    const int tg   = lane & 3;
    const int qb = blockIdx.x;
    const int h  = blockIdx.y;
    const int b  = blockIdx.z;
    const int q0 = qb * 128;
    const size_t bh = ((size_t)(b * H_ + h)) * T_ * D_;

    // load Q (cvt to tf32 RN once)
    for (int i = 0; i < 16; i++) {
        int e = tid + i * 256;
        int row = e >> 5;
        int col = (e & 31) * 4;
        float4 v = *(const float4*)(g_q + bh + (size_t)(q0 + row) * D_ + col);
        float4 w = {__uint_as_float(tf32_rn(v.x)), __uint_as_float(tf32_rn(v.y)),
                    __uint_as_float(tf32_rn(v.z)), __uint_as_float(tf32_rn(v.w))};
        *(float4*)&sQ[row * QSTR + col] = w;
    }

    float yacc[16][4];
#pragma unroll
    for (int nt = 0; nt < 16; nt++)
#pragma unroll
        for (int c = 0; c < 4; c++) yacc[nt][c] = 0.f;
    float m0 = -1e30f, m1 = -1e30f, l0 = 0.f, l1 = 0.f;

    const float* qrow0 = sQ + (size_t)(16 * warp + g) * QSTR;
    const float* qrow1 = qrow0 + 8 * QSTR;
    const float* prow0 = sP + (size_t)(16 * warp + g) * PSTR;
    const float* prow1 = prow0 + 8 * PSTR;
    float* pw0 = sP + (size_t)(16 * warp + g) * PSTR;
    float* pw1 = pw0 + 8 * PSTR;

    for (int kt = 0; kt <= qb; kt++) {
        const int k0 = kt * 128;

        // load K raw fp32, [key][d]
        for (int i = 0; i < 16; i++) {
            int e = tid + i * 256;
            int row = e >> 5;
            int col = (e & 31) * 4;
            float4 v = *(const float4*)(g_k + bh + (size_t)(k0 + row) * D_ + col);
            *(float4*)&sKV[row * KSTR + col] = v;
        }
        __syncthreads();

        // S = Q K^T
        float sacc[16][4];
#pragma unroll
        for (int nt = 0; nt < 16; nt++)
#pragma unroll
            for (int c = 0; c < 4; c++) sacc[nt][c] = 0.f;

#pragma unroll
        for (int ks = 0; ks < 16; ks++) {
            const int kk = ks * 8;
            uint32_t a[4];
            a[0] = __float_as_uint(qrow0[kk + tg]);       // already tf32
            a[1] = __float_as_uint(qrow1[kk + tg]);
            a[2] = __float_as_uint(qrow0[kk + tg + 4]);
            a[3] = __float_as_uint(qrow1[kk + tg + 4]);
#pragma unroll
            for (int nt = 0; nt < 16; nt++) {
                uint32_t bfr[2];
                bfr[0] = tf32_rn(sKV[(size_t)(nt * 8 + g) * KSTR + kk + tg]);
                bfr[1] = tf32_rn(sKV[(size_t)(nt * 8 + g) * KSTR + kk + tg + 4]);
                MMA_TF32(sacc[nt], a, bfr);
            }
        }

        // causal mask on diagonal tile
        if (kt == qb) {
            const int r0g = q0 + 16 * warp + g;
            const int r1g = r0g + 8;
#pragma unroll
            for (int nt = 0; nt < 16; nt++) {
                int c0 = k0 + nt * 8 + 2 * tg;
                if (c0     > r0g) sacc[nt][0] = -1e30f;
                if (c0 + 1 > r0g) sacc[nt][1] = -1e30f;
                if (c0     > r1g) sacc[nt][2] = -1e30f;
                if (c0 + 1 > r1g) sacc[nt][3] = -1e30f;
            }
        }

        // online softmax
        float mx0 = -1e30f, mx1 = -1e30f;
#pragma unroll
        for (int nt = 0; nt < 16; nt++) {
            mx0 = fmaxf(mx0, fmaxf(sacc[nt][0], sacc[nt][1]));
            mx1 = fmaxf(mx1, fmaxf(sacc[nt][2], sacc[nt][3]));
        }
        mx0 = fmaxf(mx0, __shfl_xor_sync(0xffffffffu, mx0, 1));
        mx0 = fmaxf(mx0, __shfl_xor_sync(0xffffffffu, mx0, 2));
        mx1 = fmaxf(mx1, __shfl_xor_sync(0xffffffffu, mx1, 1));
        mx1 = fmaxf(mx1, __shfl_xor_sync(0xffffffffu, mx1, 2));

        float nm0 = fmaxf(m0, mx0), nm1 = fmaxf(m1, mx1);
        float cf0 = __expf(m0 - nm0), cf1 = __expf(m1 - nm1);
        m0 = nm0; m1 = nm1;

        float rs0 = 0.f, rs1 = 0.f;
#pragma unroll
        for (int nt = 0; nt < 16; nt++) {
            sacc[nt][0] = __expf(sacc[nt][0] - nm0);
            sacc[nt][1] = __expf(sacc[nt][1] - nm0);
            sacc[nt][2] = __expf(sacc[nt][2] - nm1);
            sacc[nt][3] = __expf(sacc[nt][3] - nm1);
            rs0 += sacc[nt][0] + sacc[nt][1];
            rs1 += sacc[nt][2] + sacc[nt][3];
        }
        rs0 += __shfl_xor_sync(0xffffffffu, rs0, 1);
        rs0 += __shfl_xor_sync(0xffffffffu, rs0, 2);
        rs1 += __shfl_xor_sync(0xffffffffu, rs1, 1);
        rs1 += __shfl_xor_sync(0xffffffffu, rs1, 2);
        l0 = l0 * cf0 + rs0;
        l1 = l1 * cf1 + rs1;

#pragma unroll
        for (int nt = 0; nt < 16; nt++) {
            yacc[nt][0] *= cf0; yacc[nt][1] *= cf0;
            yacc[nt][2] *= cf1; yacc[nt][3] *= cf1;
        }

        // stage P (tf32 RN)
#pragma unroll
        for (int nt = 0; nt < 16; nt++) {
            int col = nt * 8 + 2 * tg;
            *(float2*)&pw0[col] = make_float2(__uint_as_float(tf32_rn(sacc[nt][0])),
                                              __uint_as_float(tf32_rn(sacc[nt][1])));
            *(float2*)&pw1[col] = make_float2(__uint_as_float(tf32_rn(sacc[nt][2])),
                                              __uint_as_float(tf32_rn(sacc[nt][3])));
        }
        __syncwarp();
        __syncthreads();

        // load V raw fp32, [key][d]
        for (int i = 0; i < 16; i++) {
            int e = tid + i * 256;
            int row = e >> 5;
            int col = (e & 31) * 4;
            float4 v = *(const float4*)(g_v + bh + (size_t)(k0 + row) * D_ + col);
            *(float4*)&sKV[row * VSTR + col] = v;
        }
        __syncthreads();

        // yacc += P V
#pragma unroll
        for (int ks = 0; ks < 16; ks++) {
            const int kk = ks * 8;
            uint32_t a[4];
            a[0] = __float_as_uint(prow0[kk + tg]);       // already tf32
            a[1] = __float_as_uint(prow1[kk + tg]);
            a[2] = __float_as_uint(prow0[kk + tg + 4]);
            a[3] = __float_as_uint(prow1[kk + tg + 4]);
#pragma unroll
            for (int nt = 0; nt < 16; nt++) {
                uint32_t bfr[2];
                bfr[0] = tf32_rn(sKV[(size_t)(kk + tg) * VSTR + nt * 8 + g]);
                bfr[1] = tf32_rn(sKV[(size_t)(kk + tg + 4) * VSTR + nt * 8 + g]);
                MMA_TF32(yacc[nt], a, bfr);
            }
        }
        __syncthreads();
    }

    // epilogue
    const float inv0 = 1.f / l0;
    const float inv1 = 1.f / l1;
    const int r0g = q0 + 16 * warp + g;
    const int r1g = r0g + 8;
#pragma unroll
    for (int nt = 0; nt < 16; nt++) {
        int col = h * D_ + nt * 8 + 2 * tg;
        float2 v0 = {yacc[nt][0] * inv0, yacc[nt][1] * inv0};
        float2 v1 = {yacc[nt][2] * inv1, yacc[nt][3] * inv1};
        *(float2*)&Y[(size_t)(b * T_ + r0g) * C_ + col] = v0;
        *(float2*)&Y[(size_t)(b * T_ + r1g) * C_ + col] = v1;
    }
}

// ---------------- launch ----------------
extern "C" void kernel_launch(void* const* d_in, const int* in_sizes, int n_in,
                              void* d_out, int out_size)
{
    const float* x     = (const float*)d_in[0];
    const float* Wqkv  = (const float*)d_in[1];
    const float* Wproj = (const float*)d_in[2];
    const float* gain  = (const float*)d_in[3];
    const float* cosb  = (const float*)d_in[4];
    const float* sinb  = (const float*)d_in[5];
    float* out = (float*)d_out;

    float *qkv, *y;
    cudaGetSymbolAddress((void**)&qkv, g_qkv);
    cudaGetSymbolAddress((void**)&y, g_y);

    const size_t gemm_smem = (size_t)4 * 128 * GSTR * sizeof(float);   // 73728
    cudaFuncSetAttribute(gemm_tf32, cudaFuncAttributeMaxDynamicSharedMemorySize, (int)gemm_smem);

    // 1) QKV GEMM
    {
        dim3 grid(F_ / 128, (B_ * T_) / 128);
        gemm_tf32<<<grid, 256, gemm_smem>>>(x, Wqkv, qkv, B_ * T_, F_, C_);
    }

    // 2) RoPE + split + gain
    {
        int total = B_ * T_ * H_ * 64;
        rope_kernel<<<total / 256, 256>>>(gain, cosb, sinb);
    }

    // 3) attention (tensor core)
    {
        size_t smem = (size_t)(128 * QSTR + 128 * VSTR + 128 * PSTR) * sizeof(float);
        cudaFuncSetAttribute(attn_tc, cudaFuncAttributeMaxDynamicSharedMemorySize, (int)smem);
        dim3 grid(T_ / 128, H_, B_);
        attn_tc<<<grid, 256, smem>>>(y);
    }

    // 4) output projection
    {
        dim3 grid(C_ / 128, (B_ * T_) / 128);
        gemm_tf32<<<grid, 256, gemm_smem>>>(y, Wproj, out, B_ * T_, C_, C_);
    }
}

// round 6
// speedup vs baseline: 4.1066x; 1.1835x over previous
#include <cuda_runtime.h>
#include <math.h>
#include <float.h>
#include <stdint.h>

#define B_ 2
#define T_ 2048
#define C_ 2048
#define H_ 16
#define D_ 128
#define F_ (3*C_)

// ---------------- scratch ----------------
__device__ float g_qkv[(size_t)B_ * T_ * F_];      // raw fp32 GEMM output
__device__ float g_q[(size_t)B_ * H_ * T_ * D_];   // tf32-rounded
__device__ float g_k[(size_t)B_ * H_ * T_ * D_];   // tf32-rounded
__device__ float g_v[(size_t)B_ * H_ * T_ * D_];   // tf32-rounded
__device__ float g_y[(size_t)B_ * T_ * C_];        // tf32-rounded
__device__ float g_xa[(size_t)B_ * T_ * C_];       // tf32-rounded x
__device__ float g_wq[(size_t)F_ * C_];            // tf32-rounded Wqkv
__device__ float g_wp[(size_t)C_ * C_];            // tf32-rounded Wproj

// ---------------- helpers ----------------
#define CVT_TF32(d, s) asm("cvt.rna.tf32.f32 %0, %1;" : "=r"(d) : "f"(s))
__device__ __forceinline__ uint32_t tf32_rn(float x) {
    uint32_t r; CVT_TF32(r, x); return r;
}
__device__ __forceinline__ float tf32f(float x) {
    return __uint_as_float(tf32_rn(x));
}

#define MMA_TF32(c, a, b)                                                     \
  asm volatile(                                                               \
      "mma.sync.aligned.m16n8k8.row.col.f32.tf32.tf32.f32 "                   \
      "{%0,%1,%2,%3}, {%4,%5,%6,%7}, {%8,%9}, {%0,%1,%2,%3};"                 \
      : "+f"((c)[0]), "+f"((c)[1]), "+f"((c)[2]), "+f"((c)[3])                \
      : "r"((a)[0]), "r"((a)[1]), "r"((a)[2]), "r"((a)[3]),                   \
        "r"((b)[0]), "r"((b)[1]))

#define LDSM_X4(r, addr)                                                      \
  asm volatile("ldmatrix.sync.aligned.m8n8.x4.shared.b16 {%0,%1,%2,%3}, [%4];"\
      : "=r"((r)[0]), "=r"((r)[1]), "=r"((r)[2]), "=r"((r)[3])                \
      : "r"(addr))

__device__ __forceinline__ uint32_t smem_u32(const void* p) {
    return (uint32_t)__cvta_generic_to_shared(p);
}
__device__ __forceinline__ void cp16(float* sdst, const float* gsrc) {
    uint32_t s = smem_u32(sdst);
    asm volatile("cp.async.cg.shared.global [%0], [%1], 16;" :: "r"(s), "l"(gsrc));
}
#define CP_COMMIT() asm volatile("cp.async.commit_group;" ::)
#define CP_WAIT1()  asm volatile("cp.async.wait_group 1;" ::)

// ---------------- tf32 pre-round convert ----------------
__global__ __launch_bounds__(256) void cvt_tf32_kernel(const float4* __restrict__ src,
                                                       float4* __restrict__ dst, int n4)
{
    int i = blockIdx.x * blockDim.x + threadIdx.x;
    if (i < n4) {
        float4 v = src[i];
        float4 w = {tf32f(v.x), tf32f(v.y), tf32f(v.z), tf32f(v.w)};
        dst[i] = w;
    }
}

// ---------------- tf32 GEMM (pre-rounded inputs): C[m][n]=sum_k A[m][k]B[n][k]
// 128x128 tile, 8 warps (2m x 4n), KS=32, cp.async 2-stage, ldmatrix fragments.
#define GSTR 36

__global__ __launch_bounds__(256, 2) void gemm_tf32(const float* __restrict__ A,
                                                    const float* __restrict__ Bm,
                                                    float* __restrict__ Cm,
                                                    int M, int N, int K)
{
    extern __shared__ float gsm[];
    float* As = gsm;                     // [2][128][GSTR]
    float* Bs = gsm + 2 * 128 * GSTR;    // [2][128][GSTR]

    const int tid  = threadIdx.x;
    const int warp = tid >> 5;
    const int lane = tid & 31;
    const int g    = lane >> 2;
    const int tg   = lane & 3;
    const int lm8  = lane & 7;
    const int lq   = lane >> 3;          // 0..3
    const int wm   = (warp & 1) * 64;
    const int wn   = (warp >> 1) * 32;
    const int m0   = blockIdx.y * 128;
    const int n0   = blockIdx.x * 128;

    const int lrow = tid >> 3;           // 0..31
    const int lc4  = (tid & 7) << 2;     // 0,4,..28

    // ldmatrix per-thread base addresses
    const uint32_t sbA = smem_u32(As);
    const uint32_t sbB = smem_u32(Bs);
    const uint32_t aBase = sbA + (uint32_t)((wm + lm8 + ((lq & 1) << 3)) * GSTR) * 4
                               + ((uint32_t)(lq >> 1) << 4);
    const uint32_t bBase = sbB + (uint32_t)((wn + lm8 + ((lq >> 1) << 3)) * GSTR) * 4
                               + ((uint32_t)(lq & 1) << 4);
    const uint32_t stageBytes = 128 * GSTR * 4;

    float acc[4][4][4];
#pragma unroll
    for (int mi = 0; mi < 4; mi++)
#pragma unroll
        for (int ni = 0; ni < 4; ni++)
#pragma unroll
            for (int c = 0; c < 4; c++) acc[mi][ni][c] = 0.f;

    auto load_stage = [&](int s, int k0) {
#pragma unroll
        for (int i = 0; i < 4; i++) {
            int row = lrow + i * 32;
            cp16(&As[(size_t)s * 128 * GSTR + row * GSTR + lc4],
                 A + (size_t)(m0 + row) * K + k0 + lc4);
            cp16(&Bs[(size_t)s * 128 * GSTR + row * GSTR + lc4],
                 Bm + (size_t)(n0 + row) * K + k0 + lc4);
        }
    };

    load_stage(0, 0);  CP_COMMIT();
    load_stage(1, 32); CP_COMMIT();
    CP_WAIT1();
    __syncthreads();

    const int nK = K / 32;
    int cur = 0;
    for (int kt = 0; kt < nK; kt++) {
        const uint32_t sOff = (uint32_t)cur * stageBytes;
#pragma unroll
        for (int ks = 0; ks < 4; ks++) {
            uint32_t af[4][4];
#pragma unroll
            for (int mi = 0; mi < 4; mi++)
                LDSM_X4(af[mi], aBase + sOff + (uint32_t)(mi * 16 * GSTR * 4) + ks * 32);
#pragma unroll
            for (int p = 0; p < 2; p++) {
                uint32_t bq[4];
                LDSM_X4(bq, bBase + sOff + (uint32_t)(p * 16 * GSTR * 4) + ks * 32);
#pragma unroll
                for (int mi = 0; mi < 4; mi++) {
                    MMA_TF32(acc[mi][2 * p],     af[mi], bq);
                    MMA_TF32(acc[mi][2 * p + 1], af[mi], bq + 2);
                }
            }
        }
        __syncthreads();
        if (kt + 2 < nK) load_stage(cur, (kt + 2) * 32);
        CP_COMMIT();
        CP_WAIT1();
        __syncthreads();
        cur ^= 1;
    }

#pragma unroll
    for (int mi = 0; mi < 4; mi++) {
#pragma unroll
        for (int ni = 0; ni < 4; ni++) {
            const int r = m0 + wm + mi * 16 + g;
            const int c = n0 + wn + ni * 8 + 2 * tg;
            float2 v0 = {acc[mi][ni][0], acc[mi][ni][1]};
            float2 v1 = {acc[mi][ni][2], acc[mi][ni][3]};
            *(float2*)&Cm[(size_t)r * N + c]       = v0;
            *(float2*)&Cm[(size_t)(r + 8) * N + c] = v1;
        }
    }
}

// ---------------- RoPE + split + gain-fold (emits tf32-rounded q/k/v) --------
__global__ __launch_bounds__(256) void rope_kernel(const float* __restrict__ gain,
                                                   const float* __restrict__ cosb,
                                                   const float* __restrict__ sinb)
{
    int idx = blockIdx.x * blockDim.x + threadIdx.x;
    int d = idx & 63;
    int h = (idx >> 6) & 15;
    int t = (idx >> 10) & 2047;
    int b = idx >> 21;

    size_t base = ((size_t)(b * T_ + t)) * F_ + h * D_;
    float c = cosb[t * 64 + d];
    float s = sinb[t * 64 + d];

    float q1 = g_qkv[base + d],            q2 = g_qkv[base + d + 64];
    float k1 = g_qkv[base + C_ + d],       k2 = g_qkv[base + C_ + d + 64];
    float v1 = g_qkv[base + 2 * C_ + d],   v2 = g_qkv[base + 2 * C_ + d + 64];

    float gn = gain[h] * rsqrtf((float)D_);
    size_t ob = ((size_t)((b * H_ + h) * T_ + t)) * D_;

    g_q[ob + d]      = tf32f((q1 * c - q2 * s) * gn);
    g_q[ob + d + 64] = tf32f((q2 * c + q1 * s) * gn);
    g_k[ob + d]      = tf32f(k1 * c - k2 * s);
    g_k[ob + d + 64] = tf32f(k2 * c + k1 * s);
    g_v[ob + d]      = tf32f(v1);
    g_v[ob + d + 64] = tf32f(v2);
}

// ---------------- tensor-core causal flash attention (pre-rounded tf32) ------
#define QSTR 132
#define KSTR 132
#define VSTR 136
#define PSTR 132

__global__ __launch_bounds__(256, 1) void attn_tc(float* __restrict__ Y)
{
    extern __shared__ float sm[];
    float* sQ  = sm;                         // [128][QSTR] tf32
    float* sKV = sm + 128 * QSTR;            // K stride KSTR / V stride VSTR
    float* sP  = sKV + 128 * VSTR;           // [128][PSTR] tf32

    const int tid  = threadIdx.x;
    const int warp = tid >> 5;
    const int lane = tid & 31;
    const int g    = lane >> 2;
    const int tg   = lane & 3;
    const int lm8  = lane & 7;
    const int lq   = lane >> 3;
    const int qb = blockIdx.x;
    const int h  = blockIdx.y;
    const int b  = blockIdx.z;
    const int q0 = qb * 128;
    const size_t bh = ((size_t)(b * H_ + h)) * T_ * D_;

    // ldmatrix base addresses
    const uint32_t sbQ = smem_u32(sQ);
    const uint32_t sbK = smem_u32(sKV);
    const uint32_t sbP = smem_u32(sP);
    const uint32_t qAddr = sbQ + (uint32_t)((16 * warp + lm8 + ((lq & 1) << 3)) * QSTR) * 4
                               + ((uint32_t)(lq >> 1) << 4);
    const uint32_t kAddr = sbK + (uint32_t)((lm8 + ((lq >> 1) << 3)) * KSTR) * 4
                               + ((uint32_t)(lq & 1) << 4);
    const uint32_t pAddr = sbP + (uint32_t)((16 * warp + lm8 + ((lq & 1) << 3)) * PSTR) * 4
                               + ((uint32_t)(lq >> 1) << 4);

    // load Q tile (already tf32)
    for (int i = 0; i < 16; i++) {
        int e = tid + i * 256;
        int row = e >> 5;
        int col = (e & 31) * 4;
        float4 v = *(const float4*)(g_q + bh + (size_t)(q0 + row) * D_ + col);
        *(float4*)&sQ[row * QSTR + col] = v;
    }

    float yacc[16][4];
#pragma unroll
    for (int nt = 0; nt < 16; nt++)
#pragma unroll
        for (int c = 0; c < 4; c++) yacc[nt][c] = 0.f;
    float m0 = -1e30f, m1 = -1e30f, l0 = 0.f, l1 = 0.f;

    float* pw0 = sP + (size_t)(16 * warp + g) * PSTR;
    float* pw1 = pw0 + 8 * PSTR;

    for (int kt = 0; kt <= qb; kt++) {
        const int k0 = kt * 128;

        // load K (already tf32), [key][d]
        for (int i = 0; i < 16; i++) {
            int e = tid + i * 256;
            int row = e >> 5;
            int col = (e & 31) * 4;
            float4 v = *(const float4*)(g_k + bh + (size_t)(k0 + row) * D_ + col);
            *(float4*)&sKV[row * KSTR + col] = v;
        }
        __syncthreads();

        // S = Q K^T
        float sacc[16][4];
#pragma unroll
        for (int nt = 0; nt < 16; nt++)
#pragma unroll
            for (int c = 0; c < 4; c++) sacc[nt][c] = 0.f;

#pragma unroll
        for (int ks = 0; ks < 16; ks++) {
            uint32_t a[4];
            LDSM_X4(a, qAddr + ks * 32);
#pragma unroll
            for (int p = 0; p < 8; p++) {
                uint32_t bq[4];
                LDSM_X4(bq, kAddr + (uint32_t)(p * 16 * KSTR * 4) + ks * 32);
                MMA_TF32(sacc[2 * p],     a, bq);
                MMA_TF32(sacc[2 * p + 1], a, bq + 2);
            }
        }

        // causal mask on diagonal tile
        if (kt == qb) {
            const int r0g = q0 + 16 * warp + g;
            const int r1g = r0g + 8;
#pragma unroll
            for (int nt = 0; nt < 16; nt++) {
                int c0 = k0 + nt * 8 + 2 * tg;
                if (c0     > r0g) sacc[nt][0] = -1e30f;
                if (c0 + 1 > r0g) sacc[nt][1] = -1e30f;
                if (c0     > r1g) sacc[nt][2] = -1e30f;
                if (c0 + 1 > r1g) sacc[nt][3] = -1e30f;
            }
        }

        // online softmax
        float mx0 = -1e30f, mx1 = -1e30f;
#pragma unroll
        for (int nt = 0; nt < 16; nt++) {
            mx0 = fmaxf(mx0, fmaxf(sacc[nt][0], sacc[nt][1]));
            mx1 = fmaxf(mx1, fmaxf(sacc[nt][2], sacc[nt][3]));
        }
        mx0 = fmaxf(mx0, __shfl_xor_sync(0xffffffffu, mx0, 1));
        mx0 = fmaxf(mx0, __shfl_xor_sync(0xffffffffu, mx0, 2));
        mx1 = fmaxf(mx1, __shfl_xor_sync(0xffffffffu, mx1, 1));
        mx1 = fmaxf(mx1, __shfl_xor_sync(0xffffffffu, mx1, 2));

        float nm0 = fmaxf(m0, mx0), nm1 = fmaxf(m1, mx1);
        float cf0 = __expf(m0 - nm0), cf1 = __expf(m1 - nm1);
        m0 = nm0; m1 = nm1;

        float rs0 = 0.f, rs1 = 0.f;
#pragma unroll
        for (int nt = 0; nt < 16; nt++) {
            sacc[nt][0] = __expf(sacc[nt][0] - nm0);
            sacc[nt][1] = __expf(sacc[nt][1] - nm0);
            sacc[nt][2] = __expf(sacc[nt][2] - nm1);
            sacc[nt][3] = __expf(sacc[nt][3] - nm1);
            rs0 += sacc[nt][0] + sacc[nt][1];
            rs1 += sacc[nt][2] + sacc[nt][3];
        }
        rs0 += __shfl_xor_sync(0xffffffffu, rs0, 1);
        rs0 += __shfl_xor_sync(0xffffffffu, rs0, 2);
        rs1 += __shfl_xor_sync(0xffffffffu, rs1, 1);
        rs1 += __shfl_xor_sync(0xffffffffu, rs1, 2);
        l0 = l0 * cf0 + rs0;
        l1 = l1 * cf1 + rs1;

#pragma unroll
        for (int nt = 0; nt < 16; nt++) {
            yacc[nt][0] *= cf0; yacc[nt][1] *= cf0;
            yacc[nt][2] *= cf1; yacc[nt][3] *= cf1;
        }

        // stage P (tf32 RN)
#pragma unroll
        for (int nt = 0; nt < 16; nt++) {
            int col = nt * 8 + 2 * tg;
            *(float2*)&pw0[col] = make_float2(tf32f(sacc[nt][0]), tf32f(sacc[nt][1]));
            *(float2*)&pw1[col] = make_float2(tf32f(sacc[nt][2]), tf32f(sacc[nt][3]));
        }
        __syncwarp();
        __syncthreads();

        // load V (already tf32), [key][d]
        for (int i = 0; i < 16; i++) {
            int e = tid + i * 256;
            int row = e >> 5;
            int col = (e & 31) * 4;
            float4 v = *(const float4*)(g_v + bh + (size_t)(k0 + row) * D_ + col);
            *(float4*)&sKV[row * VSTR + col] = v;
        }
        __syncthreads();

        // yacc += P V
#pragma unroll
        for (int ks = 0; ks < 16; ks++) {
            const int kk = ks * 8;
            uint32_t a[4];
            LDSM_X4(a, pAddr + ks * 32);
#pragma unroll
            for (int nt = 0; nt < 16; nt++) {
                uint32_t bfr[2];
                bfr[0] = __float_as_uint(sKV[(size_t)(kk + tg) * VSTR + nt * 8 + g]);
                bfr[1] = __float_as_uint(sKV[(size_t)(kk + tg + 4) * VSTR + nt * 8 + g]);
                MMA_TF32(yacc[nt], a, bfr);
            }
        }
        __syncthreads();
    }

    // epilogue: tf32-rounded y (feeds proj GEMM directly)
    const float inv0 = 1.f / l0;
    const float inv1 = 1.f / l1;
    const int r0g = q0 + 16 * warp + g;
    const int r1g = r0g + 8;
#pragma unroll
    for (int nt = 0; nt < 16; nt++) {
        int col = h * D_ + nt * 8 + 2 * tg;
        float2 v0 = {tf32f(yacc[nt][0] * inv0), tf32f(yacc[nt][1] * inv0)};
        float2 v1 = {tf32f(yacc[nt][2] * inv1), tf32f(yacc[nt][3] * inv1)};
        *(float2*)&Y[(size_t)(b * T_ + r0g) * C_ + col] = v0;
        *(float2*)&Y[(size_t)(b * T_ + r1g) * C_ + col] = v1;
    }
}

// ---------------- launch ----------------
extern "C" void kernel_launch(void* const* d_in, const int* in_sizes, int n_in,
                              void* d_out, int out_size)
{
    const float* x     = (const float*)d_in[0];
    const float* Wqkv  = (const float*)d_in[1];
    const float* Wproj = (const float*)d_in[2];
    const float* gain  = (const float*)d_in[3];
    const float* cosb  = (const float*)d_in[4];
    const float* sinb  = (const float*)d_in[5];
    float* out = (float*)d_out;

    float *qkv, *y, *xa, *wq, *wp;
    cudaGetSymbolAddress((void**)&qkv, g_qkv);
    cudaGetSymbolAddress((void**)&y,   g_y);
    cudaGetSymbolAddress((void**)&xa,  g_xa);
    cudaGetSymbolAddress((void**)&wq,  g_wq);
    cudaGetSymbolAddress((void**)&wp,  g_wp);

    const size_t gemm_smem = (size_t)4 * 128 * GSTR * sizeof(float);   // 73728
    cudaFuncSetAttribute(gemm_tf32, cudaFuncAttributeMaxDynamicSharedMemorySize, (int)gemm_smem);

    // 0) pre-round inputs to tf32
    {
        int n4x = (B_ * T_ * C_) / 4;
        cvt_tf32_kernel<<<(n4x + 255) / 256, 256>>>((const float4*)x, (float4*)xa, n4x);
        int n4q = (F_ * C_) / 4;
        cvt_tf32_kernel<<<(n4q + 255) / 256, 256>>>((const float4*)Wqkv, (float4*)wq, n4q);
        int n4p = (C_ * C_) / 4;
        cvt_tf32_kernel<<<(n4p + 255) / 256, 256>>>((const float4*)Wproj, (float4*)wp, n4p);
    }

    // 1) QKV GEMM: [4096,2048] x [6144,2048]^T -> [4096,6144]
    {
        dim3 grid(F_ / 128, (B_ * T_) / 128);
        gemm_tf32<<<grid, 256, gemm_smem>>>(xa, wq, qkv, B_ * T_, F_, C_);
    }

    // 2) RoPE + split + gain (emits tf32)
    {
        int total = B_ * T_ * H_ * 64;
        rope_kernel<<<total / 256, 256>>>(gain, cosb, sinb);
    }

    // 3) attention (tensor core)
    {
        size_t smem = (size_t)(128 * QSTR + 128 * VSTR + 128 * PSTR) * sizeof(float);
        cudaFuncSetAttribute(attn_tc, cudaFuncAttributeMaxDynamicSharedMemorySize, (int)smem);
        dim3 grid(T_ / 128, H_, B_);
        attn_tc<<<grid, 256, smem>>>(y);
    }

    // 4) output projection: [4096,2048] x [2048,2048]^T -> out
    {
        dim3 grid(C_ / 128, (B_ * T_) / 128);
        gemm_tf32<<<grid, 256, gemm_smem>>>(y, wp, out, B_ * T_, C_, C_);
    }
}